// round 1
// baseline (speedup 1.0000x reference)
#include <cuda_runtime.h>
#include <math.h>

// Problem constants
#define BATCH 2
#define SEQ   2048
#define DIM   2048
#define NH    16
#define HD    128
#define QKV_N (3*DIM)     // 6144
#define ROWS  (BATCH*SEQ) // 4096

// Scratch (device globals; allocation-free at runtime)
__device__ float g_qkv[(long long)ROWS * QKV_N];            // 25.2M floats
__device__ float g_qn[(long long)BATCH*NH*SEQ*HD];          // 8.4M
__device__ float g_kn[(long long)BATCH*NH*SEQ*HD];          // 8.4M
__device__ float g_scores[(long long)BATCH*NH*SEQ*SEQ];     // 134M (512MB)
__device__ float g_o[(long long)ROWS * DIM];                // 8.4M

// ---------------------------------------------------------------------------
// Generic fp32 GEMM: C = alpha * A @ op(B) + bias
// 128x128 block tile, 8x8 per thread, 256 threads, BK=16.
// Batched via blockIdx.z with (b,h) = (z/Hn, z%Hn) offset decomposition.
// All dims assumed multiples of tile sizes (true for this problem).
// ---------------------------------------------------------------------------
#define BM 128
#define BN 128
#define BK 16

__global__ __launch_bounds__(256, 2) void gemm_f32(
    const float* __restrict__ A, const float* __restrict__ B,
    const float* __restrict__ bias, float* __restrict__ C,
    int M, int N, int K, int lda, int ldb, int ldc,
    long long sAb, long long sAh, long long sBb, long long sBh,
    long long sCb, long long sCh, int Hn, float alpha, int transB)
{
    int z = blockIdx.z;
    int bb = z / Hn, hh = z % Hn;
    A += (long long)bb * sAb + (long long)hh * sAh;
    B += (long long)bb * sBb + (long long)hh * sBh;
    C += (long long)bb * sCb + (long long)hh * sCh;

    __shared__ float As[BK][BM];
    __shared__ float Bs[BK][BN];

    const int tid = threadIdx.x;
    const int tx = tid & 15;       // 0..15 -> column groups of 8
    const int ty = tid >> 4;       // 0..15 -> row groups of 8
    const int row0 = blockIdx.y * BM;
    const int col0 = blockIdx.x * BN;

    float acc[8][8];
    #pragma unroll
    for (int i = 0; i < 8; i++)
        #pragma unroll
        for (int j = 0; j < 8; j++) acc[i][j] = 0.f;

    for (int k0 = 0; k0 < K; k0 += BK) {
        // --- load A tile (BM x BK), store transposed As[k][m] ---
        #pragma unroll
        for (int it = 0; it < 2; it++) {
            int f = tid + it * 256;          // 512 float4 total
            int r = f >> 2;                  // row within tile
            int c = (f & 3) << 2;            // k within tile (float4)
            float4 v = *(const float4*)(A + (long long)(row0 + r) * lda + k0 + c);
            As[c + 0][r] = v.x; As[c + 1][r] = v.y;
            As[c + 2][r] = v.z; As[c + 3][r] = v.w;
        }
        // --- load B tile ---
        if (!transB) {
            // B[K,N] row-major: tile rows = k, cols = n
            #pragma unroll
            for (int it = 0; it < 2; it++) {
                int f = tid + it * 256;
                int r = f >> 5;               // k within tile (0..15)
                int c = (f & 31) << 2;        // n within tile
                *(float4*)(&Bs[r][c]) =
                    *(const float4*)(B + (long long)(k0 + r) * ldb + col0 + c);
            }
        } else {
            // B[N,K] row-major (NT): tile rows = n, cols = k
            #pragma unroll
            for (int it = 0; it < 2; it++) {
                int f = tid + it * 256;
                int r = f >> 2;               // n within tile (0..127)
                int c = (f & 3) << 2;         // k within tile
                float4 v = *(const float4*)(B + (long long)(col0 + r) * ldb + k0 + c);
                Bs[c + 0][r] = v.x; Bs[c + 1][r] = v.y;
                Bs[c + 2][r] = v.z; Bs[c + 3][r] = v.w;
            }
        }
        __syncthreads();

        #pragma unroll
        for (int kk = 0; kk < BK; kk++) {
            float a[8], b[8];
            *(float4*)&a[0] = *(float4*)&As[kk][ty * 8];
            *(float4*)&a[4] = *(float4*)&As[kk][ty * 8 + 4];
            *(float4*)&b[0] = *(float4*)&Bs[kk][tx * 8];
            *(float4*)&b[4] = *(float4*)&Bs[kk][tx * 8 + 4];
            #pragma unroll
            for (int i = 0; i < 8; i++)
                #pragma unroll
                for (int j = 0; j < 8; j++)
                    acc[i][j] += a[i] * b[j];
        }
        __syncthreads();
    }

    // epilogue
    #pragma unroll
    for (int i = 0; i < 8; i++) {
        long long r = row0 + ty * 8 + i;
        #pragma unroll
        for (int j = 0; j < 8; j += 4) {
            int cidx = col0 + tx * 8 + j;
            float4 v;
            v.x = acc[i][j + 0] * alpha;
            v.y = acc[i][j + 1] * alpha;
            v.z = acc[i][j + 2] * alpha;
            v.w = acc[i][j + 3] * alpha;
            if (bias) {
                v.x += bias[cidx + 0]; v.y += bias[cidx + 1];
                v.z += bias[cidx + 2]; v.w += bias[cidx + 3];
            }
            *(float4*)(C + r * ldc + cidx) = v;
        }
    }
}

// ---------------------------------------------------------------------------
// Per-(b,h,l) RMSNorm + RoPE for Q and K rows (D=128, one thread per d).
// ---------------------------------------------------------------------------
__global__ __launch_bounds__(128) void rmsnorm_rope(
    const float* __restrict__ qkv, const float* __restrict__ pe,
    const float* __restrict__ q_scale, const float* __restrict__ k_scale,
    float* __restrict__ Qn, float* __restrict__ Kn)
{
    int idx = blockIdx.x;                 // [0, B*H*L)
    int l = idx % SEQ;
    int h = (idx / SEQ) % NH;
    int b = idx / (SEQ * NH);
    int d = threadIdx.x;                  // 0..127
    int lane = d & 31, wid = d >> 5;

    const float* row = qkv + (long long)(b * SEQ + l) * QKV_N + h * HD;
    float qv = row[d];
    float kv = row[DIM + d];

    float sq = qv * qv;
    float sk = kv * kv;
    #pragma unroll
    for (int o = 16; o > 0; o >>= 1) {
        sq += __shfl_xor_sync(0xffffffffu, sq, o);
        sk += __shfl_xor_sync(0xffffffffu, sk, o);
    }
    __shared__ float sh[8];
    if (lane == 0) { sh[wid] = sq; sh[4 + wid] = sk; }
    __syncthreads();
    float ssq = sh[0] + sh[1] + sh[2] + sh[3];
    float ssk = sh[4] + sh[5] + sh[6] + sh[7];

    float rq = rsqrtf(ssq * (1.0f / HD) + 1e-6f);
    float rk = rsqrtf(ssk * (1.0f / HD) + 1e-6f);
    float qn = qv * rq * q_scale[d];
    float kn = kv * rk * k_scale[d];

    // RoPE: pe layout [L, D/2, 2, 2]
    int d2 = d >> 1, ii = d & 1;
    const float* rot = pe + ((long long)l * (HD / 2) + d2) * 4 + ii * 2;
    float qp = __shfl_xor_sync(0xffffffffu, qn, 1);
    float kp = __shfl_xor_sync(0xffffffffu, kn, 1);
    float qe = (ii == 0) ? qn : qp;
    float qo = (ii == 0) ? qp : qn;
    float ke = (ii == 0) ? kn : kp;
    float ko = (ii == 0) ? kp : kn;
    float qr = rot[0] * qe + rot[1] * qo;
    float kr = rot[0] * ke + rot[1] * ko;

    long long out = (((long long)(b * NH + h)) * SEQ + l) * HD + d;
    Qn[out] = qr;
    Kn[out] = kr;
}

// ---------------------------------------------------------------------------
// Row softmax over 2048 elements, one block (256 threads) per row.
// ---------------------------------------------------------------------------
__global__ __launch_bounds__(256) void softmax_rows(float* __restrict__ S)
{
    long long rowi = blockIdx.x;
    float* p = S + rowi * SEQ;
    int t = threadIdx.x;
    int lane = t & 31, wid = t >> 5;
    __shared__ float red[8];

    float v[8];
    float m = -1e30f;
    #pragma unroll
    for (int i = 0; i < 8; i++) { v[i] = p[t + i * 256]; m = fmaxf(m, v[i]); }
    #pragma unroll
    for (int o = 16; o > 0; o >>= 1) m = fmaxf(m, __shfl_xor_sync(0xffffffffu, m, o));
    if (lane == 0) red[wid] = m;
    __syncthreads();
    m = fmaxf(fmaxf(fmaxf(red[0], red[1]), fmaxf(red[2], red[3])),
              fmaxf(fmaxf(red[4], red[5]), fmaxf(red[6], red[7])));
    __syncthreads();

    float s = 0.f;
    #pragma unroll
    for (int i = 0; i < 8; i++) { v[i] = __expf(v[i] - m); s += v[i]; }
    #pragma unroll
    for (int o = 16; o > 0; o >>= 1) s += __shfl_xor_sync(0xffffffffu, s, o);
    if (lane == 0) red[wid] = s;
    __syncthreads();
    s = red[0] + red[1] + red[2] + red[3] + red[4] + red[5] + red[6] + red[7];
    float inv = 1.0f / s;
    #pragma unroll
    for (int i = 0; i < 8; i++) p[t + i * 256] = v[i] * inv;
}

// ---------------------------------------------------------------------------
extern "C" void kernel_launch(void* const* d_in, const int* in_sizes, int n_in,
                              void* d_out, int out_size)
{
    const float* x       = (const float*)d_in[0];
    const float* pe      = (const float*)d_in[1];
    const float* qkv_w   = (const float*)d_in[2];
    const float* qkv_b   = (const float*)d_in[3];
    const float* q_scale = (const float*)d_in[4];
    const float* k_scale = (const float*)d_in[5];
    const float* proj_w  = (const float*)d_in[6];
    const float* proj_b  = (const float*)d_in[7];
    float* out = (float*)d_out;

    float *qkv, *Qn, *Kn, *S, *O;
    cudaGetSymbolAddress((void**)&qkv, g_qkv);
    cudaGetSymbolAddress((void**)&Qn,  g_qn);
    cudaGetSymbolAddress((void**)&Kn,  g_kn);
    cudaGetSymbolAddress((void**)&S,   g_scores);
    cudaGetSymbolAddress((void**)&O,   g_o);

    dim3 blk(256);

    // 1) qkv = x @ qkv_w + qkv_b   [4096 x 6144], K=2048
    gemm_f32<<<dim3(QKV_N / BN, ROWS / BM, 1), blk>>>(
        x, qkv_w, qkv_b, qkv,
        ROWS, QKV_N, DIM, DIM, QKV_N, QKV_N,
        0, 0, 0, 0, 0, 0, 1, 1.0f, 0);

    // 2) RMSNorm + RoPE -> Qn, Kn  [B,H,L,D]
    rmsnorm_rope<<<BATCH * NH * SEQ, 128>>>(qkv, pe, q_scale, k_scale, Qn, Kn);

    // 3) scores = (Qn @ Kn^T) / sqrt(D)   per (b,h): [2048 x 2048], K=128
    gemm_f32<<<dim3(SEQ / BN, SEQ / BM, BATCH * NH), blk>>>(
        Qn, Kn, nullptr, S,
        SEQ, SEQ, HD, HD, HD, SEQ,
        (long long)SEQ * HD, 0,
        (long long)SEQ * HD, 0,
        (long long)SEQ * SEQ, 0,
        1, 0.08838834764831845f, 1);

    // 4) softmax rows
    softmax_rows<<<BATCH * NH * SEQ, 256>>>(S);

    // 5) O = P @ V  per (b,h): [2048 x 128], K=2048. V strided inside qkv.
    //    C written directly in [b, l, h*D + d] layout for the projection.
    gemm_f32<<<dim3(HD / BN, SEQ / BM, BATCH * NH), blk>>>(
        S, qkv + 2 * DIM, nullptr, O,
        SEQ, HD, SEQ, SEQ, QKV_N, DIM,
        (long long)NH * SEQ * SEQ, (long long)SEQ * SEQ,
        (long long)SEQ * QKV_N,   (long long)HD,
        (long long)SEQ * DIM,     (long long)HD,
        NH, 1.0f, 0);

    // 6) out = O @ proj_w + proj_b   [4096 x 2048], K=2048
    gemm_f32<<<dim3(DIM / BN, ROWS / BM, 1), blk>>>(
        O, proj_w, proj_b, out,
        ROWS, DIM, DIM, DIM, DIM, DIM,
        0, 0, 0, 0, 0, 0, 1, 1.0f, 0);
}

// round 2
// speedup vs baseline: 2.8427x; 2.8427x over previous
#include <cuda_runtime.h>
#include <math.h>
#include <stdint.h>

// Problem constants
#define BATCH 2
#define SEQ   2048
#define DIM   2048
#define NH    16
#define HD    128
#define QKV_N (3*DIM)     // 6144
#define ROWS  (BATCH*SEQ) // 4096

// Scratch (device globals; allocation-free at runtime)
__device__ float g_qkv[(long long)ROWS * QKV_N];
__device__ float g_qn[(long long)BATCH*NH*SEQ*HD];
__device__ float g_kn[(long long)BATCH*NH*SEQ*HD];
__device__ float g_scores[(long long)BATCH*NH*SEQ*SEQ];
__device__ float g_o[(long long)ROWS * DIM];

// ---------------------------------------------------------------------------
// tf32 tensor-core GEMM:  C = alpha * A @ op(B) + bias
// 128x128 block tile, BK=32, 8 warps (256 thr), warp tile 32x64,
// mma.sync.m16n8k8.tf32.  Batched via blockIdx.z.
// ---------------------------------------------------------------------------
#define BM 128
#define BN 128
#define BK 32
#define LDA_S 36     // A smem: [m][k], 36 floats/row (conflict-free, 16B-mult)
#define LDBT_S 36    // B^T smem: [n][k]
#define LDBK_S 136   // B smem (NN): [k][n]

__device__ __forceinline__ uint32_t f2tf32(float x) {
    uint32_t u;
    asm("cvt.rna.tf32.f32 %0, %1;" : "=r"(u) : "f"(x));
    return u;
}

__device__ __forceinline__ void mma_tf32(float& d0, float& d1, float& d2, float& d3,
                                         uint32_t a0, uint32_t a1, uint32_t a2, uint32_t a3,
                                         uint32_t b0, uint32_t b1) {
    asm volatile(
        "mma.sync.aligned.m16n8k8.row.col.f32.tf32.tf32.f32 "
        "{%0,%1,%2,%3}, {%4,%5,%6,%7}, {%8,%9}, {%0,%1,%2,%3};"
        : "+f"(d0), "+f"(d1), "+f"(d2), "+f"(d3)
        : "r"(a0), "r"(a1), "r"(a2), "r"(a3), "r"(b0), "r"(b1));
}

template<int TRANSB>
__global__ __launch_bounds__(256, 2) void gemm_tf32(
    const float* __restrict__ A, const float* __restrict__ B,
    const float* __restrict__ bias, float* __restrict__ C,
    int K, int lda, int ldb, int ldc,
    long long sAb, long long sAh, long long sBb, long long sBh,
    long long sCb, long long sCh, int Hn, float alpha)
{
    int z = blockIdx.z;
    int bb = z / Hn, hh = z % Hn;
    A += (long long)bb * sAb + (long long)hh * sAh;
    B += (long long)bb * sBb + (long long)hh * sBh;
    C += (long long)bb * sCb + (long long)hh * sCh;

    __shared__ float As[BM * LDA_S];                       // 18432 B
    __shared__ float Bs[BM * LDBT_S];                      // 18432 B (covers 32*136=4352 floats too)

    const int tid  = threadIdx.x;
    const int lane = tid & 31;
    const int warp = tid >> 5;
    const int wm = warp & 3;          // 4 warps over M -> 32 rows each
    const int wn = warp >> 2;         // 2 warps over N -> 64 cols each
    const int row0 = blockIdx.y * BM;
    const int col0 = blockIdx.x * BN;
    const int l4 = lane & 3;
    const int l2 = lane >> 2;

    float acc[2][8][4];
    #pragma unroll
    for (int i = 0; i < 2; i++)
        #pragma unroll
        for (int j = 0; j < 8; j++)
            #pragma unroll
            for (int q = 0; q < 4; q++) acc[i][j][q] = 0.f;

    const uint32_t* Au = (const uint32_t*)As;
    const uint32_t* Bu = (const uint32_t*)Bs;

    for (int k0 = 0; k0 < K; k0 += BK) {
        // ---- A tile: gmem [m][k] row-major -> smem [m][k] ld=36 ----
        #pragma unroll
        for (int it = 0; it < 4; it++) {
            int f = tid + it * 256;            // 0..1023
            int r  = f >> 3;                   // 0..127
            int c4 = (f & 7) * 4;              // 0..28
            float4 v = *(const float4*)(A + (long long)(row0 + r) * lda + k0 + c4);
            uint4 t;
            t.x = f2tf32(v.x); t.y = f2tf32(v.y);
            t.z = f2tf32(v.z); t.w = f2tf32(v.w);
            *(uint4*)&As[r * LDA_S + c4] = t;
        }
        // ---- B tile ----
        if (TRANSB) {
            // B[n][k] row-major -> smem [n][k] ld=36
            #pragma unroll
            for (int it = 0; it < 4; it++) {
                int f = tid + it * 256;
                int r  = f >> 3;
                int c4 = (f & 7) * 4;
                float4 v = *(const float4*)(B + (long long)(col0 + r) * ldb + k0 + c4);
                uint4 t;
                t.x = f2tf32(v.x); t.y = f2tf32(v.y);
                t.z = f2tf32(v.z); t.w = f2tf32(v.w);
                *(uint4*)&Bs[r * LDBT_S + c4] = t;
            }
        } else {
            // B[k][n] row-major -> smem [k][n] ld=136
            #pragma unroll
            for (int it = 0; it < 4; it++) {
                int f = tid + it * 256;        // 0..1023
                int kr = f >> 5;               // 0..31
                int c4 = (f & 31) * 4;         // 0..124
                float4 v = *(const float4*)(B + (long long)(k0 + kr) * ldb + col0 + c4);
                uint4 t;
                t.x = f2tf32(v.x); t.y = f2tf32(v.y);
                t.z = f2tf32(v.z); t.w = f2tf32(v.w);
                *(uint4*)&Bs[kr * LDBK_S + c4] = t;
            }
        }
        __syncthreads();

        #pragma unroll
        for (int kk = 0; kk < BK; kk += 8) {
            uint32_t a[2][4], b[8][2];
            #pragma unroll
            for (int mf = 0; mf < 2; mf++) {
                int mb = wm * 32 + mf * 16 + l2;
                a[mf][0] = Au[ mb      * LDA_S + kk     + l4];
                a[mf][1] = Au[(mb + 8) * LDA_S + kk     + l4];
                a[mf][2] = Au[ mb      * LDA_S + kk + 4 + l4];
                a[mf][3] = Au[(mb + 8) * LDA_S + kk + 4 + l4];
            }
            #pragma unroll
            for (int nf = 0; nf < 8; nf++) {
                int nb = wn * 64 + nf * 8 + l2;
                if (TRANSB) {
                    b[nf][0] = Bu[nb * LDBT_S + kk     + l4];
                    b[nf][1] = Bu[nb * LDBT_S + kk + 4 + l4];
                } else {
                    b[nf][0] = Bu[(kk     + l4) * LDBK_S + nb];
                    b[nf][1] = Bu[(kk + 4 + l4) * LDBK_S + nb];
                }
            }
            #pragma unroll
            for (int mf = 0; mf < 2; mf++)
                #pragma unroll
                for (int nf = 0; nf < 8; nf++)
                    mma_tf32(acc[mf][nf][0], acc[mf][nf][1],
                             acc[mf][nf][2], acc[mf][nf][3],
                             a[mf][0], a[mf][1], a[mf][2], a[mf][3],
                             b[nf][0], b[nf][1]);
        }
        __syncthreads();
    }

    // ---- epilogue ----
    #pragma unroll
    for (int mf = 0; mf < 2; mf++) {
        long long r0 = row0 + wm * 32 + mf * 16 + l2;
        long long r1 = r0 + 8;
        #pragma unroll
        for (int nf = 0; nf < 8; nf++) {
            int col = col0 + wn * 64 + nf * 8 + 2 * l4;
            float bx = 0.f, by = 0.f;
            if (bias) { bx = bias[col]; by = bias[col + 1]; }
            float2 v0 = { acc[mf][nf][0] * alpha + bx, acc[mf][nf][1] * alpha + by };
            float2 v1 = { acc[mf][nf][2] * alpha + bx, acc[mf][nf][3] * alpha + by };
            *(float2*)(C + r0 * ldc + col) = v0;
            *(float2*)(C + r1 * ldc + col) = v1;
        }
    }
}

// ---------------------------------------------------------------------------
// Per-(b,h,l) RMSNorm + RoPE for Q and K rows (D=128, one thread per d).
// ---------------------------------------------------------------------------
__global__ __launch_bounds__(128) void rmsnorm_rope(
    const float* __restrict__ qkv, const float* __restrict__ pe,
    const float* __restrict__ q_scale, const float* __restrict__ k_scale,
    float* __restrict__ Qn, float* __restrict__ Kn)
{
    int idx = blockIdx.x;                 // [0, B*H*L)
    int l = idx % SEQ;
    int h = (idx / SEQ) % NH;
    int b = idx / (SEQ * NH);
    int d = threadIdx.x;                  // 0..127
    int lane = d & 31, wid = d >> 5;

    const float* row = qkv + (long long)(b * SEQ + l) * QKV_N + h * HD;
    float qv = row[d];
    float kv = row[DIM + d];

    float sq = qv * qv;
    float sk = kv * kv;
    #pragma unroll
    for (int o = 16; o > 0; o >>= 1) {
        sq += __shfl_xor_sync(0xffffffffu, sq, o);
        sk += __shfl_xor_sync(0xffffffffu, sk, o);
    }
    __shared__ float sh[8];
    if (lane == 0) { sh[wid] = sq; sh[4 + wid] = sk; }
    __syncthreads();
    float ssq = sh[0] + sh[1] + sh[2] + sh[3];
    float ssk = sh[4] + sh[5] + sh[6] + sh[7];

    float rq = rsqrtf(ssq * (1.0f / HD) + 1e-6f);
    float rk = rsqrtf(ssk * (1.0f / HD) + 1e-6f);
    float qn = qv * rq * q_scale[d];
    float kn = kv * rk * k_scale[d];

    int d2 = d >> 1, ii = d & 1;
    const float* rot = pe + ((long long)l * (HD / 2) + d2) * 4 + ii * 2;
    float qp = __shfl_xor_sync(0xffffffffu, qn, 1);
    float kp = __shfl_xor_sync(0xffffffffu, kn, 1);
    float qe = (ii == 0) ? qn : qp;
    float qo = (ii == 0) ? qp : qn;
    float ke = (ii == 0) ? kn : kp;
    float ko = (ii == 0) ? kp : kn;
    float qr = rot[0] * qe + rot[1] * qo;
    float kr = rot[0] * ke + rot[1] * ko;

    long long out = (((long long)(b * NH + h)) * SEQ + l) * HD + d;
    Qn[out] = qr;
    Kn[out] = kr;
}

// ---------------------------------------------------------------------------
// Row softmax over 2048 elements, one block (256 threads) per row.
// ---------------------------------------------------------------------------
__global__ __launch_bounds__(256) void softmax_rows(float* __restrict__ S)
{
    long long rowi = blockIdx.x;
    float* p = S + rowi * SEQ;
    int t = threadIdx.x;
    int lane = t & 31, wid = t >> 5;
    __shared__ float red[8];

    float v[8];
    float m = -1e30f;
    #pragma unroll
    for (int i = 0; i < 8; i++) { v[i] = p[t + i * 256]; m = fmaxf(m, v[i]); }
    #pragma unroll
    for (int o = 16; o > 0; o >>= 1) m = fmaxf(m, __shfl_xor_sync(0xffffffffu, m, o));
    if (lane == 0) red[wid] = m;
    __syncthreads();
    m = fmaxf(fmaxf(fmaxf(red[0], red[1]), fmaxf(red[2], red[3])),
              fmaxf(fmaxf(red[4], red[5]), fmaxf(red[6], red[7])));
    __syncthreads();

    float s = 0.f;
    #pragma unroll
    for (int i = 0; i < 8; i++) { v[i] = __expf(v[i] - m); s += v[i]; }
    #pragma unroll
    for (int o = 16; o > 0; o >>= 1) s += __shfl_xor_sync(0xffffffffu, s, o);
    if (lane == 0) red[wid] = s;
    __syncthreads();
    s = red[0] + red[1] + red[2] + red[3] + red[4] + red[5] + red[6] + red[7];
    float inv = 1.0f / s;
    #pragma unroll
    for (int i = 0; i < 8; i++) p[t + i * 256] = v[i] * inv;
}

// ---------------------------------------------------------------------------
extern "C" void kernel_launch(void* const* d_in, const int* in_sizes, int n_in,
                              void* d_out, int out_size)
{
    const float* x       = (const float*)d_in[0];
    const float* pe      = (const float*)d_in[1];
    const float* qkv_w   = (const float*)d_in[2];
    const float* qkv_b   = (const float*)d_in[3];
    const float* q_scale = (const float*)d_in[4];
    const float* k_scale = (const float*)d_in[5];
    const float* proj_w  = (const float*)d_in[6];
    const float* proj_b  = (const float*)d_in[7];
    float* out = (float*)d_out;

    float *qkv, *Qn, *Kn, *S, *O;
    cudaGetSymbolAddress((void**)&qkv, g_qkv);
    cudaGetSymbolAddress((void**)&Qn,  g_qn);
    cudaGetSymbolAddress((void**)&Kn,  g_kn);
    cudaGetSymbolAddress((void**)&S,   g_scores);
    cudaGetSymbolAddress((void**)&O,   g_o);

    dim3 blk(256);

    // 1) qkv = x @ qkv_w + qkv_b   [4096 x 6144], K=2048
    gemm_tf32<0><<<dim3(QKV_N / BN, ROWS / BM, 1), blk>>>(
        x, qkv_w, qkv_b, qkv,
        DIM, DIM, QKV_N, QKV_N,
        0, 0, 0, 0, 0, 0, 1, 1.0f);

    // 2) RMSNorm + RoPE -> Qn, Kn  [B,H,L,D]
    rmsnorm_rope<<<BATCH * NH * SEQ, 128>>>(qkv, pe, q_scale, k_scale, Qn, Kn);

    // 3) scores = (Qn @ Kn^T) / sqrt(D)   per (b,h): [2048 x 2048], K=128
    gemm_tf32<1><<<dim3(SEQ / BN, SEQ / BM, BATCH * NH), blk>>>(
        Qn, Kn, nullptr, S,
        HD, HD, HD, SEQ,
        (long long)SEQ * HD, 0,
        (long long)SEQ * HD, 0,
        (long long)SEQ * SEQ, 0,
        1, 0.08838834764831845f);

    // 4) softmax rows
    softmax_rows<<<BATCH * NH * SEQ, 256>>>(S);

    // 5) O = P @ V  per (b,h): [2048 x 128], K=2048. V strided inside qkv.
    gemm_tf32<0><<<dim3(HD / BN, SEQ / BM, BATCH * NH), blk>>>(
        S, qkv + 2 * DIM, nullptr, O,
        SEQ, SEQ, QKV_N, DIM,
        (long long)NH * SEQ * SEQ, (long long)SEQ * SEQ,
        (long long)SEQ * QKV_N,   (long long)HD,
        (long long)SEQ * DIM,     (long long)HD,
        NH, 1.0f);

    // 6) out = O @ proj_w + proj_b   [4096 x 2048], K=2048
    gemm_tf32<0><<<dim3(DIM / BN, ROWS / BM, 1), blk>>>(
        O, proj_w, proj_b, out,
        DIM, DIM, DIM, DIM,
        0, 0, 0, 0, 0, 0, 1, 1.0f);
}

// round 3
// speedup vs baseline: 6.7823x; 2.3859x over previous
#include <cuda_runtime.h>
#include <cuda_fp16.h>
#include <math.h>
#include <stdint.h>

#define BATCH 2
#define SEQ   2048
#define DIM   2048
#define NH    16
#define HD    128
#define QKV_N (3*DIM)
#define ROWS  (BATCH*SEQ)

// ---------------- scratch (device globals) ----------------
__device__ __half g_xh[(long long)ROWS * DIM];
__device__ __half g_wqkvh[(long long)DIM * QKV_N];
__device__ __half g_wprojh[(long long)DIM * DIM];
__device__ float  g_qkv[(long long)ROWS * QKV_N];
__device__ __half g_qnh[(long long)BATCH*NH*SEQ*HD];
__device__ __half g_knh[(long long)BATCH*NH*SEQ*HD];
__device__ __half g_vh [(long long)BATCH*NH*SEQ*HD];
__device__ __half g_oh [(long long)ROWS * DIM];

// ---------------- PTX helpers ----------------
__device__ __forceinline__ uint32_t smem_u32(const void* p) {
    return (uint32_t)__cvta_generic_to_shared(p);
}
__device__ __forceinline__ void ldsm_x4(uint32_t& r0, uint32_t& r1, uint32_t& r2, uint32_t& r3, uint32_t a) {
    asm volatile("ldmatrix.sync.aligned.m8n8.x4.shared.b16 {%0,%1,%2,%3}, [%4];"
                 : "=r"(r0), "=r"(r1), "=r"(r2), "=r"(r3) : "r"(a));
}
__device__ __forceinline__ void ldsm_x4_t(uint32_t& r0, uint32_t& r1, uint32_t& r2, uint32_t& r3, uint32_t a) {
    asm volatile("ldmatrix.sync.aligned.m8n8.x4.trans.shared.b16 {%0,%1,%2,%3}, [%4];"
                 : "=r"(r0), "=r"(r1), "=r"(r2), "=r"(r3) : "r"(a));
}
__device__ __forceinline__ void mma_f16(float* d, const uint32_t* a, uint32_t b0, uint32_t b1) {
    asm volatile("mma.sync.aligned.m16n8k16.row.col.f32.f16.f16.f32 "
                 "{%0,%1,%2,%3}, {%4,%5,%6,%7}, {%8,%9}, {%0,%1,%2,%3};"
                 : "+f"(d[0]), "+f"(d[1]), "+f"(d[2]), "+f"(d[3])
                 : "r"(a[0]), "r"(a[1]), "r"(a[2]), "r"(a[3]), "r"(b0), "r"(b1));
}
__device__ __forceinline__ void cp16(uint32_t dst, const void* src) {
    asm volatile("cp.async.cg.shared.global [%0], [%1], 16;" :: "r"(dst), "l"(src));
}
__device__ __forceinline__ void cp_commit() { asm volatile("cp.async.commit_group;"); }
__device__ __forceinline__ uint32_t pack_h2(float x, float y) {
    __half2 h = __floats2half2_rn(x, y);
    return *(uint32_t*)&h;
}

// ---------------- fp32 -> fp16 converters ----------------
__global__ __launch_bounds__(256) void f32_to_f16(const float* __restrict__ s,
                                                  __half* __restrict__ d, long long n8)
{
    long long i = (long long)blockIdx.x * 256 + threadIdx.x;
    if (i >= n8) return;
    const float4* s4 = (const float4*)s;
    float4 v0 = s4[2*i], v1 = s4[2*i + 1];
    uint4 o;
    o.x = pack_h2(v0.x, v0.y); o.y = pack_h2(v0.z, v0.w);
    o.z = pack_h2(v1.x, v1.y); o.w = pack_h2(v1.z, v1.w);
    ((uint4*)d)[i] = o;
}

// V slice of qkv (fp32, strided) -> Vh [b,h,key,d] fp16 contiguous
__global__ __launch_bounds__(256) void conv_v(const float* __restrict__ qkv,
                                              __half* __restrict__ Vh)
{
    long long idx = (long long)blockIdx.x * 256 + threadIdx.x; // BATCH*NH*SEQ*32
    int j = (int)(idx & 31);
    long long bhk = idx >> 5;
    int key = (int)(bhk % SEQ);
    int h   = (int)((bhk / SEQ) % NH);
    int b   = (int)(bhk / ((long long)SEQ * NH));
    float4 v = *(const float4*)(qkv + ((long long)(b * SEQ + key)) * QKV_N + 2 * DIM + h * HD + j * 4);
    uint2 o;
    o.x = pack_h2(v.x, v.y);
    o.y = pack_h2(v.z, v.w);
    *(uint2*)(Vh + bhk * HD + j * 4) = o;
}

// ---------------------------------------------------------------------------
// fp16 GEMM (NN): C_f32 = A_h[M,K] @ B_h[K,N] + bias.  128x128x32, 2-stage cp.async.
// ---------------------------------------------------------------------------
#define GBM 128
#define GBN 128
#define GBK 32
#define LDA_H 40
#define LDB_H 136

__global__ __launch_bounds__(256, 2) void gemm_f16(
    const __half* __restrict__ A, const __half* __restrict__ B,
    const float* __restrict__ bias, float* __restrict__ C,
    int K, int lda, int ldb, int ldc)
{
    __shared__ __half As[2][GBM * LDA_H];   // 20480 B
    __shared__ __half Bs[2][GBK * LDB_H];   // 17408 B

    const int tid = threadIdx.x, lane = tid & 31, warp = tid >> 5;
    const int wm = warp & 3, wn = warp >> 2;
    const long long row0 = (long long)blockIdx.y * GBM;
    const long long col0 = (long long)blockIdx.x * GBN;

    float acc[2][8][4];
    #pragma unroll
    for (int i = 0; i < 2; i++)
        #pragma unroll
        for (int j = 0; j < 8; j++)
            #pragma unroll
            for (int q = 0; q < 4; q++) acc[i][j][q] = 0.f;

    const int ar = tid >> 2,  ac = (tid & 3) * 8;    // A: 128 rows x 32 halves (2 chunks/thread)
    const int br = tid >> 4,  bc = (tid & 15) * 8;   // B: 32 rows x 128 halves

    auto load_stage = [&](int bufi, int k0) {
        #pragma unroll
        for (int it = 0; it < 2; it++) {
            int r = ar + it * 64;
            cp16(smem_u32(&As[bufi][r * LDA_H + ac]), A + (row0 + r) * lda + k0 + ac);
        }
        #pragma unroll
        for (int it = 0; it < 2; it++) {
            int r = br + it * 16;
            cp16(smem_u32(&Bs[bufi][r * LDB_H + bc]), B + (long long)(k0 + r) * ldb + col0 + bc);
        }
    };

    load_stage(0, 0);
    cp_commit();

    const int arow = (lane & 7) + 8 * ((lane >> 3) & 1);
    const int acolb = ((lane >> 4) & 1) * 8;
    const int brow = (lane & 7) + 8 * ((lane >> 3) & 1);
    const int bcolb = ((lane >> 4) & 1) * 8;

    int buf = 0;
    for (int k0 = 0; k0 < K; k0 += GBK) {
        bool more = (k0 + GBK) < K;
        if (more) { load_stage(buf ^ 1, k0 + GBK); cp_commit(); }
        if (more) asm volatile("cp.async.wait_group 1;");
        else      asm volatile("cp.async.wait_group 0;");
        __syncthreads();

        uint32_t aB = smem_u32(&As[buf][0]);
        uint32_t bB = smem_u32(&Bs[buf][0]);
        #pragma unroll
        for (int kk = 0; kk < 2; kk++) {
            uint32_t af[2][4];
            #pragma unroll
            for (int mf = 0; mf < 2; mf++) {
                int r = wm * 32 + mf * 16 + arow;
                int c = kk * 16 + acolb;
                ldsm_x4(af[mf][0], af[mf][1], af[mf][2], af[mf][3], aB + (r * LDA_H + c) * 2);
            }
            #pragma unroll
            for (int nfp = 0; nfp < 4; nfp++) {
                uint32_t b0, b1, b2, b3;
                int r = kk * 16 + brow;
                int c = wn * 64 + nfp * 16 + bcolb;
                ldsm_x4_t(b0, b1, b2, b3, bB + (r * LDB_H + c) * 2);
                #pragma unroll
                for (int mf = 0; mf < 2; mf++) {
                    mma_f16(acc[mf][2 * nfp],     af[mf], b0, b1);
                    mma_f16(acc[mf][2 * nfp + 1], af[mf], b2, b3);
                }
            }
        }
        __syncthreads();
        buf ^= 1;
    }

    const int l4 = lane & 3, l2 = lane >> 2;
    #pragma unroll
    for (int mf = 0; mf < 2; mf++) {
        long long r0 = row0 + wm * 32 + mf * 16 + l2;
        long long r1 = r0 + 8;
        #pragma unroll
        for (int nf = 0; nf < 8; nf++) {
            long long col = col0 + wn * 64 + nf * 8 + 2 * l4;
            float bx = bias ? bias[col] : 0.f, by = bias ? bias[col + 1] : 0.f;
            float2 v0 = { acc[mf][nf][0] + bx, acc[mf][nf][1] + by };
            float2 v1 = { acc[mf][nf][2] + bx, acc[mf][nf][3] + by };
            *(float2*)(C + r0 * ldc + col) = v0;
            *(float2*)(C + r1 * ldc + col) = v1;
        }
    }
}

// ---------------------------------------------------------------------------
// RMSNorm + RoPE -> fp16 Q/K in [b,h,l,d]
// ---------------------------------------------------------------------------
__global__ __launch_bounds__(128) void rmsnorm_rope(
    const float* __restrict__ qkv, const float* __restrict__ pe,
    const float* __restrict__ q_scale, const float* __restrict__ k_scale,
    __half* __restrict__ Qn, __half* __restrict__ Kn)
{
    int idx = blockIdx.x;
    int l = idx % SEQ;
    int h = (idx / SEQ) % NH;
    int b = idx / (SEQ * NH);
    int d = threadIdx.x;
    int lane = d & 31, wid = d >> 5;

    const float* row = qkv + (long long)(b * SEQ + l) * QKV_N + h * HD;
    float qv = row[d];
    float kv = row[DIM + d];

    float sq = qv * qv, sk = kv * kv;
    #pragma unroll
    for (int o = 16; o > 0; o >>= 1) {
        sq += __shfl_xor_sync(0xffffffffu, sq, o);
        sk += __shfl_xor_sync(0xffffffffu, sk, o);
    }
    __shared__ float sh[8];
    if (lane == 0) { sh[wid] = sq; sh[4 + wid] = sk; }
    __syncthreads();
    float ssq = sh[0] + sh[1] + sh[2] + sh[3];
    float ssk = sh[4] + sh[5] + sh[6] + sh[7];

    float rq = rsqrtf(ssq * (1.0f / HD) + 1e-6f);
    float rk = rsqrtf(ssk * (1.0f / HD) + 1e-6f);
    float qn = qv * rq * q_scale[d];
    float kn = kv * rk * k_scale[d];

    int d2 = d >> 1, ii = d & 1;
    const float* rot = pe + ((long long)l * (HD / 2) + d2) * 4 + ii * 2;
    float qp = __shfl_xor_sync(0xffffffffu, qn, 1);
    float kp = __shfl_xor_sync(0xffffffffu, kn, 1);
    float qe = (ii == 0) ? qn : qp;
    float qo = (ii == 0) ? qp : qn;
    float ke = (ii == 0) ? kn : kp;
    float ko = (ii == 0) ? kp : kn;
    float qr = rot[0] * qe + rot[1] * qo;
    float kr = rot[0] * ke + rot[1] * ko;

    long long out = (((long long)(b * NH + h)) * SEQ + l) * HD + d;
    Qn[out] = __float2half(qr);
    Kn[out] = __float2half(kr);
}

// ---------------------------------------------------------------------------
// Flash attention: per CTA 128 Q-rows x full head. 8 warps, warp = 16 rows x 128.
// Online softmax fp32; P stays in registers. K/V double-buffered cp.async.
// ---------------------------------------------------------------------------
#define LDQ 136
#define FTILES (SEQ / 128)   // 16

__global__ __launch_bounds__(256, 1) void flash_attn(
    const __half* __restrict__ Qh, const __half* __restrict__ Kh,
    const __half* __restrict__ Vh, __half* __restrict__ Oh)
{
    extern __shared__ __half sm[];
    __half* Qs = sm;                  // 128*136
    __half* Ks = Qs + 128 * LDQ;      // 2 bufs
    __half* Vs = Ks + 2 * 128 * LDQ;  // 2 bufs

    const int tid = threadIdx.x, lane = tid & 31, wq = tid >> 5;
    const int bh = blockIdx.y;
    const int b = bh >> 4, h = bh & 15;
    const long long base = (long long)bh * SEQ * HD;
    const __half* Qp = Qh + base + (long long)blockIdx.x * 128 * HD;
    const __half* Kp = Kh + base;
    const __half* Vp = Vh + base;

    const int cr = tid >> 4, cc = (tid & 15) * 8;   // 128x256B tile: 8 chunks/thread

    // Q load (group 0)
    #pragma unroll
    for (int it = 0; it < 8; it++) {
        int r = cr + it * 16;
        cp16(smem_u32(Qs + r * LDQ + cc), Qp + (long long)r * HD + cc);
    }
    cp_commit();

    auto load_kv = [&](int bufi, int t) {
        const __half* kp = Kp + (long long)t * 128 * HD;
        const __half* vp = Vp + (long long)t * 128 * HD;
        __half* kd = Ks + bufi * 128 * LDQ;
        __half* vd = Vs + bufi * 128 * LDQ;
        #pragma unroll
        for (int it = 0; it < 8; it++) {
            int r = cr + it * 16;
            cp16(smem_u32(kd + r * LDQ + cc), kp + (long long)r * HD + cc);
        }
        #pragma unroll
        for (int it = 0; it < 8; it++) {
            int r = cr + it * 16;
            cp16(smem_u32(vd + r * LDQ + cc), vp + (long long)r * HD + cc);
        }
    };

    load_kv(0, 0);
    cp_commit();

    asm volatile("cp.async.wait_group 1;");   // Q done
    __syncthreads();

    // preload Q fragments (iter-invariant)
    uint32_t qf[8][4];
    {
        int r = wq * 16 + (lane & 7) + 8 * ((lane >> 3) & 1);
        int c = ((lane >> 4) & 1) * 8;
        uint32_t qB = smem_u32(Qs);
        #pragma unroll
        for (int kk = 0; kk < 8; kk++)
            ldsm_x4(qf[kk][0], qf[kk][1], qf[kk][2], qf[kk][3],
                    qB + (r * LDQ + kk * 16 + c) * 2);
    }

    float oacc[16][4];
    #pragma unroll
    for (int i = 0; i < 16; i++)
        #pragma unroll
        for (int j = 0; j < 4; j++) oacc[i][j] = 0.f;
    float m0 = -INFINITY, m1 = -INFINITY, l0 = 0.f, l1 = 0.f;

    const int rowS = (lane & 7) + 8 * ((lane >> 4) & 1);   // bit4 -> n(+8)
    const int colS = ((lane >> 3) & 1) * 8;                // bit3 -> k half
    const int rowV = (lane & 7) + 8 * ((lane >> 3) & 1);   // bit3 -> k(+8)
    const int colV = ((lane >> 4) & 1) * 8;                // bit4 -> n half
    const uint32_t kB0 = smem_u32(Ks), vB0 = smem_u32(Vs);
    const float CSCALE = 0.08838834764831845f * 1.4426950408889634f; // /sqrt(128) * log2(e)

    int buf = 0;
    for (int t = 0; t < FTILES; t++) {
        if (t + 1 < FTILES) { load_kv(buf ^ 1, t + 1); cp_commit(); }
        if (t + 1 < FTILES) asm volatile("cp.async.wait_group 1;");
        else                asm volatile("cp.async.wait_group 0;");
        __syncthreads();

        uint32_t kB = kB0 + buf * (128 * LDQ * 2);
        uint32_t vB = vB0 + buf * (128 * LDQ * 2);

        float sacc[16][4];
        #pragma unroll
        for (int i = 0; i < 16; i++)
            #pragma unroll
            for (int j = 0; j < 4; j++) sacc[i][j] = 0.f;

        // S = Q @ K^T
        #pragma unroll
        for (int nfp = 0; nfp < 8; nfp++) {
            uint32_t baseN = kB + ((16 * nfp + rowS) * LDQ + colS) * 2;
            #pragma unroll
            for (int kk = 0; kk < 8; kk++) {
                uint32_t b0, b1, b2, b3;
                ldsm_x4(b0, b1, b2, b3, baseN + kk * 32);  // 16 halves = 32 B
                mma_f16(sacc[2 * nfp],     qf[kk], b0, b1);
                mma_f16(sacc[2 * nfp + 1], qf[kk], b2, b3);
            }
        }

        // online softmax (log2 domain)
        float mt0 = -INFINITY, mt1 = -INFINITY;
        #pragma unroll
        for (int nf = 0; nf < 16; nf++) {
            sacc[nf][0] *= CSCALE; sacc[nf][1] *= CSCALE;
            sacc[nf][2] *= CSCALE; sacc[nf][3] *= CSCALE;
            mt0 = fmaxf(mt0, fmaxf(sacc[nf][0], sacc[nf][1]));
            mt1 = fmaxf(mt1, fmaxf(sacc[nf][2], sacc[nf][3]));
        }
        #pragma unroll
        for (int o = 1; o <= 2; o <<= 1) {
            mt0 = fmaxf(mt0, __shfl_xor_sync(0xffffffffu, mt0, o));
            mt1 = fmaxf(mt1, __shfl_xor_sync(0xffffffffu, mt1, o));
        }
        float mn0 = fmaxf(m0, mt0), mn1 = fmaxf(m1, mt1);
        float cor0 = exp2f(m0 - mn0), cor1 = exp2f(m1 - mn1);
        m0 = mn0; m1 = mn1;

        float rs0 = 0.f, rs1 = 0.f;
        #pragma unroll
        for (int nf = 0; nf < 16; nf++) {
            sacc[nf][0] = exp2f(sacc[nf][0] - mn0);
            sacc[nf][1] = exp2f(sacc[nf][1] - mn0);
            sacc[nf][2] = exp2f(sacc[nf][2] - mn1);
            sacc[nf][3] = exp2f(sacc[nf][3] - mn1);
            rs0 += sacc[nf][0] + sacc[nf][1];
            rs1 += sacc[nf][2] + sacc[nf][3];
        }
        l0 = l0 * cor0 + rs0;
        l1 = l1 * cor1 + rs1;
        #pragma unroll
        for (int nf = 0; nf < 16; nf++) {
            oacc[nf][0] *= cor0; oacc[nf][1] *= cor0;
            oacc[nf][2] *= cor1; oacc[nf][3] *= cor1;
        }

        // O += P @ V   (P from registers)
        #pragma unroll
        for (int kk = 0; kk < 8; kk++) {
            uint32_t af[4];
            af[0] = pack_h2(sacc[2 * kk][0],     sacc[2 * kk][1]);
            af[1] = pack_h2(sacc[2 * kk][2],     sacc[2 * kk][3]);
            af[2] = pack_h2(sacc[2 * kk + 1][0], sacc[2 * kk + 1][1]);
            af[3] = pack_h2(sacc[2 * kk + 1][2], sacc[2 * kk + 1][3]);
            uint32_t baseK = vB + ((16 * kk + rowV) * LDQ + colV) * 2;
            #pragma unroll
            for (int nfp = 0; nfp < 8; nfp++) {
                uint32_t b0, b1, b2, b3;
                ldsm_x4_t(b0, b1, b2, b3, baseK + nfp * 32);
                mma_f16(oacc[2 * nfp],     af, b0, b1);
                mma_f16(oacc[2 * nfp + 1], af, b2, b3);
            }
        }
        __syncthreads();
        buf ^= 1;
    }

    // finalize
    #pragma unroll
    for (int o = 1; o <= 2; o <<= 1) {
        l0 += __shfl_xor_sync(0xffffffffu, l0, o);
        l1 += __shfl_xor_sync(0xffffffffu, l1, o);
    }
    float inv0 = 1.0f / l0, inv1 = 1.0f / l1;

    const int l4 = lane & 3, l2 = lane >> 2;
    long long q0 = (long long)blockIdx.x * 128 + wq * 16 + l2;
    #pragma unroll
    for (int nf = 0; nf < 16; nf++) {
        int col = nf * 8 + 2 * l4;
        long long o0 = ((long long)b * SEQ + q0) * DIM + h * HD + col;
        long long o1 = o0 + 8LL * DIM;
        *(uint32_t*)(Oh + o0) = pack_h2(oacc[nf][0] * inv0, oacc[nf][1] * inv0);
        *(uint32_t*)(Oh + o1) = pack_h2(oacc[nf][2] * inv1, oacc[nf][3] * inv1);
    }
}

// ---------------------------------------------------------------------------
extern "C" void kernel_launch(void* const* d_in, const int* in_sizes, int n_in,
                              void* d_out, int out_size)
{
    const float* x       = (const float*)d_in[0];
    const float* pe      = (const float*)d_in[1];
    const float* qkv_w   = (const float*)d_in[2];
    const float* qkv_b   = (const float*)d_in[3];
    const float* q_scale = (const float*)d_in[4];
    const float* k_scale = (const float*)d_in[5];
    const float* proj_w  = (const float*)d_in[6];
    const float* proj_b  = (const float*)d_in[7];
    float* out = (float*)d_out;

    __half *xh, *wqkvh, *wprojh, *Qnh, *Knh, *Vh, *Oh;
    float* qkv;
    cudaGetSymbolAddress((void**)&xh,     g_xh);
    cudaGetSymbolAddress((void**)&wqkvh,  g_wqkvh);
    cudaGetSymbolAddress((void**)&wprojh, g_wprojh);
    cudaGetSymbolAddress((void**)&qkv,    g_qkv);
    cudaGetSymbolAddress((void**)&Qnh,    g_qnh);
    cudaGetSymbolAddress((void**)&Knh,    g_knh);
    cudaGetSymbolAddress((void**)&Vh,     g_vh);
    cudaGetSymbolAddress((void**)&Oh,     g_oh);

    static const int FLASH_SMEM = 5 * 128 * LDQ * 2; // 174080
    cudaFuncSetAttribute(flash_attn, cudaFuncAttributeMaxDynamicSharedMemorySize, FLASH_SMEM);

    // 0) convert inputs to fp16
    {
        long long n8;
        n8 = (long long)ROWS * DIM / 8;
        f32_to_f16<<<(unsigned)((n8 + 255) / 256), 256>>>(x, xh, n8);
        n8 = (long long)DIM * QKV_N / 8;
        f32_to_f16<<<(unsigned)((n8 + 255) / 256), 256>>>(qkv_w, wqkvh, n8);
        n8 = (long long)DIM * DIM / 8;
        f32_to_f16<<<(unsigned)((n8 + 255) / 256), 256>>>(proj_w, wprojh, n8);
    }

    // 1) qkv = x @ qkv_w + qkv_b   (fp32 out)
    gemm_f16<<<dim3(QKV_N / GBN, ROWS / GBM), 256>>>(
        xh, wqkvh, qkv_b, qkv, DIM, DIM, QKV_N, QKV_N);

    // 2) RMSNorm + RoPE -> fp16 Q/K ; V slice -> fp16
    rmsnorm_rope<<<BATCH * NH * SEQ, 128>>>(qkv, pe, q_scale, k_scale, Qnh, Knh);
    {
        long long nt = (long long)BATCH * NH * SEQ * 32;
        conv_v<<<(unsigned)(nt / 256), 256>>>(qkv, Vh);
    }

    // 3) fused flash attention -> Oh fp16 in [b, l, h*D+d]
    flash_attn<<<dim3(SEQ / 128, BATCH * NH), 256, FLASH_SMEM>>>(Qnh, Knh, Vh, Oh);

    // 4) out = O @ proj_w + proj_b
    gemm_f16<<<dim3(DIM / GBN, ROWS / GBM), 256>>>(
        Oh, wprojh, proj_b, out, DIM, DIM, DIM, DIM);
}

// round 4
// speedup vs baseline: 6.8475x; 1.0096x over previous
#include <cuda_runtime.h>
#include <cuda_fp16.h>
#include <math.h>
#include <stdint.h>

#define BATCH 2
#define SEQ   2048
#define DIM   2048
#define NH    16
#define HD    128
#define QKV_N (3*DIM)
#define ROWS  (BATCH*SEQ)

// ---------------- scratch (device globals) ----------------
__device__ __half g_xh[(long long)ROWS * DIM];
__device__ __half g_wqkvh[(long long)DIM * QKV_N];
__device__ __half g_wprojh[(long long)DIM * DIM];
__device__ __half g_qnh[(long long)BATCH*NH*SEQ*HD];
__device__ __half g_knh[(long long)BATCH*NH*SEQ*HD];
__device__ __half g_vh [(long long)BATCH*NH*SEQ*HD];
__device__ __half g_oh [(long long)ROWS * DIM];

// ---------------- PTX helpers ----------------
__device__ __forceinline__ uint32_t smem_u32(const void* p) {
    return (uint32_t)__cvta_generic_to_shared(p);
}
__device__ __forceinline__ void ldsm_x4(uint32_t& r0, uint32_t& r1, uint32_t& r2, uint32_t& r3, uint32_t a) {
    asm volatile("ldmatrix.sync.aligned.m8n8.x4.shared.b16 {%0,%1,%2,%3}, [%4];"
                 : "=r"(r0), "=r"(r1), "=r"(r2), "=r"(r3) : "r"(a));
}
__device__ __forceinline__ void ldsm_x4_t(uint32_t& r0, uint32_t& r1, uint32_t& r2, uint32_t& r3, uint32_t a) {
    asm volatile("ldmatrix.sync.aligned.m8n8.x4.trans.shared.b16 {%0,%1,%2,%3}, [%4];"
                 : "=r"(r0), "=r"(r1), "=r"(r2), "=r"(r3) : "r"(a));
}
__device__ __forceinline__ void mma_f16(float* d, const uint32_t* a, uint32_t b0, uint32_t b1) {
    asm volatile("mma.sync.aligned.m16n8k16.row.col.f32.f16.f16.f32 "
                 "{%0,%1,%2,%3}, {%4,%5,%6,%7}, {%8,%9}, {%0,%1,%2,%3};"
                 : "+f"(d[0]), "+f"(d[1]), "+f"(d[2]), "+f"(d[3])
                 : "r"(a[0]), "r"(a[1]), "r"(a[2]), "r"(a[3]), "r"(b0), "r"(b1));
}
__device__ __forceinline__ void cp16(uint32_t dst, const void* src) {
    asm volatile("cp.async.cg.shared.global [%0], [%1], 16;" :: "r"(dst), "l"(src));
}
__device__ __forceinline__ void cp_commit() { asm volatile("cp.async.commit_group;"); }
__device__ __forceinline__ uint32_t pack_h2(float x, float y) {
    __half2 h = __floats2half2_rn(x, y);
    return *(uint32_t*)&h;
}

// ---------------- fp32 -> fp16 converter ----------------
__global__ __launch_bounds__(256) void f32_to_f16(const float* __restrict__ s,
                                                  __half* __restrict__ d, long long n8)
{
    long long i = (long long)blockIdx.x * 256 + threadIdx.x;
    if (i >= n8) return;
    const float4* s4 = (const float4*)s;
    float4 v0 = s4[2*i], v1 = s4[2*i + 1];
    uint4 o;
    o.x = pack_h2(v0.x, v0.y); o.y = pack_h2(v0.z, v0.w);
    o.z = pack_h2(v1.x, v1.y); o.w = pack_h2(v1.z, v1.w);
    ((uint4*)d)[i] = o;
}

// ---------------------------------------------------------------------------
// fp16 GEMM (NN), 128x128x32, 3-stage cp.async pipeline.
// MODE 0: C_f32 = A@B + bias.
// MODE 1: fused QKV epilogue — per 128-col tile (= one head of Q/K/V):
//         Q/K: +bias, RMSNorm(row), RoPE, fp16 -> Qn/Kn [b,h,l,d]
//         V:   +bias, fp16 -> Vh [b,h,l,d]
// ---------------------------------------------------------------------------
#define GBM 128
#define GBN 128
#define GBK 32
#define LDA_H 40
#define LDB_H 136
#define STG_A (GBM * LDA_H)      // halves
#define STG_B (GBK * LDB_H)
#define STG_SZ (STG_A + STG_B)   // 9472 halves
#define NSTG 3
#define GEMM_SMEM (NSTG * STG_SZ * 2)  // 56832 B

template<int MODE>
__global__ __launch_bounds__(256, 2) void gemm_f16(
    const __half* __restrict__ A, const __half* __restrict__ B,
    const float* __restrict__ bias, float* __restrict__ C,
    int K, int lda, int ldb, int ldc,
    const float* __restrict__ pe,
    const float* __restrict__ q_scale, const float* __restrict__ k_scale,
    __half* __restrict__ Qn, __half* __restrict__ Kn, __half* __restrict__ Vh)
{
    extern __shared__ __half dynsm[];

    const int tid = threadIdx.x, lane = tid & 31, warp = tid >> 5;
    const int wm = warp & 3, wn = warp >> 2;
    const long long row0 = (long long)blockIdx.y * GBM;
    const long long col0 = (long long)blockIdx.x * GBN;

    float acc[2][8][4];
    #pragma unroll
    for (int i = 0; i < 2; i++)
        #pragma unroll
        for (int j = 0; j < 8; j++)
            #pragma unroll
            for (int q = 0; q < 4; q++) acc[i][j][q] = 0.f;

    const int ar = tid >> 2,  ac = (tid & 3) * 8;
    const int br = tid >> 4,  bc = (tid & 15) * 8;

    auto load_stage = [&](int s, int k0) {
        __half* As = dynsm + s * STG_SZ;
        __half* Bs = As + STG_A;
        #pragma unroll
        for (int it = 0; it < 2; it++) {
            int r = ar + it * 64;
            cp16(smem_u32(&As[r * LDA_H + ac]), A + (row0 + r) * lda + k0 + ac);
        }
        #pragma unroll
        for (int it = 0; it < 2; it++) {
            int r = br + it * 16;
            cp16(smem_u32(&Bs[r * LDB_H + bc]), B + (long long)(k0 + r) * ldb + col0 + bc);
        }
    };

    load_stage(0, 0); cp_commit();
    load_stage(1, GBK); cp_commit();

    const int arow = (lane & 7) + 8 * ((lane >> 3) & 1);
    const int acolb = ((lane >> 4) & 1) * 8;
    const int brow = (lane & 7) + 8 * ((lane >> 3) & 1);
    const int bcolb = ((lane >> 4) & 1) * 8;

    const int nsteps = K / GBK;
    int buf = 0;
    for (int s = 0; s < nsteps; s++) {
        asm volatile("cp.async.wait_group 1;");
        __syncthreads();

        if (s + 2 < nsteps) load_stage((buf + 2) % NSTG, (s + 2) * GBK);
        cp_commit();

        uint32_t aB = smem_u32(dynsm + buf * STG_SZ);
        uint32_t bB = smem_u32(dynsm + buf * STG_SZ + STG_A);
        #pragma unroll
        for (int kk = 0; kk < 2; kk++) {
            uint32_t af[2][4];
            #pragma unroll
            for (int mf = 0; mf < 2; mf++) {
                int r = wm * 32 + mf * 16 + arow;
                int c = kk * 16 + acolb;
                ldsm_x4(af[mf][0], af[mf][1], af[mf][2], af[mf][3], aB + (r * LDA_H + c) * 2);
            }
            #pragma unroll
            for (int nfp = 0; nfp < 4; nfp++) {
                uint32_t b0, b1, b2, b3;
                int r = kk * 16 + brow;
                int c = wn * 64 + nfp * 16 + bcolb;
                ldsm_x4_t(b0, b1, b2, b3, bB + (r * LDB_H + c) * 2);
                #pragma unroll
                for (int mf = 0; mf < 2; mf++) {
                    mma_f16(acc[mf][2 * nfp],     af[mf], b0, b1);
                    mma_f16(acc[mf][2 * nfp + 1], af[mf], b2, b3);
                }
            }
        }
        buf = (buf + 1) % NSTG;
    }

    const int l4 = lane & 3, l2 = lane >> 2;

    // bias add (both modes)
    #pragma unroll
    for (int mf = 0; mf < 2; mf++)
        #pragma unroll
        for (int nf = 0; nf < 8; nf++) {
            long long col = col0 + wn * 64 + nf * 8 + 2 * l4;
            float bx = bias[col], by = bias[col + 1];
            acc[mf][nf][0] += bx; acc[mf][nf][1] += by;
            acc[mf][nf][2] += bx; acc[mf][nf][3] += by;
        }

    if (MODE == 0) {
        #pragma unroll
        for (int mf = 0; mf < 2; mf++) {
            long long r0 = row0 + wm * 32 + mf * 16 + l2;
            long long r1 = r0 + 8;
            #pragma unroll
            for (int nf = 0; nf < 8; nf++) {
                long long col = col0 + wn * 64 + nf * 8 + 2 * l4;
                float2 v0 = { acc[mf][nf][0], acc[mf][nf][1] };
                float2 v1 = { acc[mf][nf][2], acc[mf][nf][3] };
                *(float2*)(C + r0 * ldc + col) = v0;
                *(float2*)(C + r1 * ldc + col) = v1;
            }
        }
        return;
    }

    // ---- MODE 1: fused QKV epilogue ----
    const int col0i = (int)col0;
    const int seg = col0i >> 11;             // 0:Q 1:K 2:V
    const int hh  = (col0i & 2047) >> 7;     // head
    __syncthreads();                          // stage buffers free now
    float* red = (float*)dynsm;               // [128][2]

    if (seg < 2) {
        // row sum of squares: 4 rows per lane: (mf, half)
        #pragma unroll
        for (int mf = 0; mf < 2; mf++) {
            float s0 = 0.f, s1 = 0.f;
            #pragma unroll
            for (int nf = 0; nf < 8; nf++) {
                s0 += acc[mf][nf][0] * acc[mf][nf][0] + acc[mf][nf][1] * acc[mf][nf][1];
                s1 += acc[mf][nf][2] * acc[mf][nf][2] + acc[mf][nf][3] * acc[mf][nf][3];
            }
            #pragma unroll
            for (int o = 1; o <= 2; o <<= 1) {
                s0 += __shfl_xor_sync(0xffffffffu, s0, o);
                s1 += __shfl_xor_sync(0xffffffffu, s1, o);
            }
            if (l4 == 0) {
                int rl = wm * 32 + mf * 16 + l2;
                red[rl * 2 + wn] = s0;
                red[(rl + 8) * 2 + wn] = s1;
            }
        }
        __syncthreads();

        const float* scale = (seg == 0) ? q_scale : k_scale;
        __half* Out = (seg == 0) ? Qn : Kn;

        #pragma unroll
        for (int mf = 0; mf < 2; mf++) {
            #pragma unroll
            for (int half = 0; half < 2; half++) {
                int rl = wm * 32 + mf * 16 + half * 8 + l2;
                long long grow = row0 + rl;
                int b = (int)(grow >> 11), l = (int)(grow & 2047);
                float rms = rsqrtf((red[rl * 2] + red[rl * 2 + 1]) * (1.0f / HD) + 1e-6f);
                long long obase = (((long long)(b * NH + hh)) * SEQ + l) * HD;
                const float* perow = pe + (long long)l * (HD * 2);
                #pragma unroll
                for (int nf = 0; nf < 8; nf++) {
                    int dcol = wn * 64 + nf * 8 + 2 * l4;
                    float e = acc[mf][nf][half * 2]     * rms * scale[dcol];
                    float o = acc[mf][nf][half * 2 + 1] * rms * scale[dcol + 1];
                    float4 rot = *(const float4*)(perow + (dcol >> 1) * 4);
                    float oe = rot.x * e + rot.y * o;
                    float oo = rot.z * e + rot.w * o;
                    *(uint32_t*)(Out + obase + dcol) = pack_h2(oe, oo);
                }
            }
        }
    } else {
        #pragma unroll
        for (int mf = 0; mf < 2; mf++) {
            #pragma unroll
            for (int half = 0; half < 2; half++) {
                int rl = wm * 32 + mf * 16 + half * 8 + l2;
                long long grow = row0 + rl;
                int b = (int)(grow >> 11), l = (int)(grow & 2047);
                long long obase = (((long long)(b * NH + hh)) * SEQ + l) * HD;
                #pragma unroll
                for (int nf = 0; nf < 8; nf++) {
                    int dcol = wn * 64 + nf * 8 + 2 * l4;
                    *(uint32_t*)(Vh + obase + dcol) =
                        pack_h2(acc[mf][nf][half * 2], acc[mf][nf][half * 2 + 1]);
                }
            }
        }
    }
}

// ---------------------------------------------------------------------------
// Flash attention: CTA = 128 Q-rows x full head; KV tile 64, double-buffered.
// 8 warps, warp = 16 Q-rows. P stays in registers.
// ---------------------------------------------------------------------------
#define LDQ 136
#define KVT 64
#define FTILES (SEQ / KVT)   // 32
#define FLASH_SMEM ((128 * LDQ + 4 * KVT * LDQ) * 2)   // 104448 B

__global__ __launch_bounds__(256, 2) void flash_attn(
    const __half* __restrict__ Qh, const __half* __restrict__ Kh,
    const __half* __restrict__ Vh, __half* __restrict__ Oh)
{
    extern __shared__ __half sm[];
    __half* Qs = sm;                     // 128*LDQ
    __half* Ks = Qs + 128 * LDQ;         // 2 bufs of 64*LDQ
    __half* Vs = Ks + 2 * KVT * LDQ;     // 2 bufs

    const int tid = threadIdx.x, lane = tid & 31, wq = tid >> 5;
    const int bh = blockIdx.y;
    const int b = bh >> 4, h = bh & 15;
    const long long base = (long long)bh * SEQ * HD;
    const __half* Qp = Qh + base + (long long)blockIdx.x * 128 * HD;
    const __half* Kp = Kh + base;
    const __half* Vp = Vh + base;

    const int cr = tid >> 4, cc = (tid & 15) * 8;

    #pragma unroll
    for (int it = 0; it < 8; it++) {
        int r = cr + it * 16;
        cp16(smem_u32(Qs + r * LDQ + cc), Qp + (long long)r * HD + cc);
    }
    cp_commit();

    auto load_kv = [&](int bufi, int t) {
        const __half* kp = Kp + (long long)t * KVT * HD;
        const __half* vp = Vp + (long long)t * KVT * HD;
        __half* kd = Ks + bufi * KVT * LDQ;
        __half* vd = Vs + bufi * KVT * LDQ;
        #pragma unroll
        for (int it = 0; it < 4; it++) {
            int r = cr + it * 16;
            cp16(smem_u32(kd + r * LDQ + cc), kp + (long long)r * HD + cc);
        }
        #pragma unroll
        for (int it = 0; it < 4; it++) {
            int r = cr + it * 16;
            cp16(smem_u32(vd + r * LDQ + cc), vp + (long long)r * HD + cc);
        }
    };

    load_kv(0, 0);
    cp_commit();

    asm volatile("cp.async.wait_group 1;");
    __syncthreads();

    uint32_t qf[8][4];
    {
        int r = wq * 16 + (lane & 7) + 8 * ((lane >> 3) & 1);
        int c = ((lane >> 4) & 1) * 8;
        uint32_t qB = smem_u32(Qs);
        #pragma unroll
        for (int kk = 0; kk < 8; kk++)
            ldsm_x4(qf[kk][0], qf[kk][1], qf[kk][2], qf[kk][3],
                    qB + (r * LDQ + kk * 16 + c) * 2);
    }

    float oacc[16][4];
    #pragma unroll
    for (int i = 0; i < 16; i++)
        #pragma unroll
        for (int j = 0; j < 4; j++) oacc[i][j] = 0.f;
    float m0 = -INFINITY, m1 = -INFINITY, l0 = 0.f, l1 = 0.f;

    const int rowS = (lane & 7) + 8 * ((lane >> 4) & 1);
    const int colS = ((lane >> 3) & 1) * 8;
    const int rowV = (lane & 7) + 8 * ((lane >> 3) & 1);
    const int colV = ((lane >> 4) & 1) * 8;
    const uint32_t kB0 = smem_u32(Ks), vB0 = smem_u32(Vs);
    const float CSCALE = 0.08838834764831845f * 1.4426950408889634f;

    int buf = 0;
    for (int t = 0; t < FTILES; t++) {
        if (t + 1 < FTILES) { load_kv(buf ^ 1, t + 1); cp_commit(); }
        if (t + 1 < FTILES) asm volatile("cp.async.wait_group 1;");
        else                asm volatile("cp.async.wait_group 0;");
        __syncthreads();

        uint32_t kB = kB0 + buf * (KVT * LDQ * 2);
        uint32_t vB = vB0 + buf * (KVT * LDQ * 2);

        float sacc[8][4];
        #pragma unroll
        for (int i = 0; i < 8; i++)
            #pragma unroll
            for (int j = 0; j < 4; j++) sacc[i][j] = 0.f;

        #pragma unroll
        for (int nfp = 0; nfp < 4; nfp++) {
            uint32_t baseN = kB + ((16 * nfp + rowS) * LDQ + colS) * 2;
            #pragma unroll
            for (int kk = 0; kk < 8; kk++) {
                uint32_t b0, b1, b2, b3;
                ldsm_x4(b0, b1, b2, b3, baseN + kk * 32);
                mma_f16(sacc[2 * nfp],     qf[kk], b0, b1);
                mma_f16(sacc[2 * nfp + 1], qf[kk], b2, b3);
            }
        }

        float mt0 = -INFINITY, mt1 = -INFINITY;
        #pragma unroll
        for (int nf = 0; nf < 8; nf++) {
            sacc[nf][0] *= CSCALE; sacc[nf][1] *= CSCALE;
            sacc[nf][2] *= CSCALE; sacc[nf][3] *= CSCALE;
            mt0 = fmaxf(mt0, fmaxf(sacc[nf][0], sacc[nf][1]));
            mt1 = fmaxf(mt1, fmaxf(sacc[nf][2], sacc[nf][3]));
        }
        #pragma unroll
        for (int o = 1; o <= 2; o <<= 1) {
            mt0 = fmaxf(mt0, __shfl_xor_sync(0xffffffffu, mt0, o));
            mt1 = fmaxf(mt1, __shfl_xor_sync(0xffffffffu, mt1, o));
        }
        float mn0 = fmaxf(m0, mt0), mn1 = fmaxf(m1, mt1);
        float cor0 = exp2f(m0 - mn0), cor1 = exp2f(m1 - mn1);
        m0 = mn0; m1 = mn1;

        float rs0 = 0.f, rs1 = 0.f;
        #pragma unroll
        for (int nf = 0; nf < 8; nf++) {
            sacc[nf][0] = exp2f(sacc[nf][0] - mn0);
            sacc[nf][1] = exp2f(sacc[nf][1] - mn0);
            sacc[nf][2] = exp2f(sacc[nf][2] - mn1);
            sacc[nf][3] = exp2f(sacc[nf][3] - mn1);
            rs0 += sacc[nf][0] + sacc[nf][1];
            rs1 += sacc[nf][2] + sacc[nf][3];
        }
        l0 = l0 * cor0 + rs0;
        l1 = l1 * cor1 + rs1;
        #pragma unroll
        for (int nf = 0; nf < 8; nf++) {
            oacc[2*nf][0] *= 1.f;  // keep structure; scaling below over 16 tiles
        }
        #pragma unroll
        for (int nf = 0; nf < 16; nf++) {
            oacc[nf][0] *= cor0; oacc[nf][1] *= cor0;
            oacc[nf][2] *= cor1; oacc[nf][3] *= cor1;
        }

        #pragma unroll
        for (int kk = 0; kk < 4; kk++) {
            uint32_t af[4];
            af[0] = pack_h2(sacc[2 * kk][0],     sacc[2 * kk][1]);
            af[1] = pack_h2(sacc[2 * kk][2],     sacc[2 * kk][3]);
            af[2] = pack_h2(sacc[2 * kk + 1][0], sacc[2 * kk + 1][1]);
            af[3] = pack_h2(sacc[2 * kk + 1][2], sacc[2 * kk + 1][3]);
            uint32_t baseK = vB + ((16 * kk + rowV) * LDQ + colV) * 2;
            #pragma unroll
            for (int nfp = 0; nfp < 8; nfp++) {
                uint32_t b0, b1, b2, b3;
                ldsm_x4_t(b0, b1, b2, b3, baseK + nfp * 32);
                mma_f16(oacc[2 * nfp],     af, b0, b1);
                mma_f16(oacc[2 * nfp + 1], af, b2, b3);
            }
        }
        __syncthreads();
        buf ^= 1;
    }

    #pragma unroll
    for (int o = 1; o <= 2; o <<= 1) {
        l0 += __shfl_xor_sync(0xffffffffu, l0, o);
        l1 += __shfl_xor_sync(0xffffffffu, l1, o);
    }
    float inv0 = 1.0f / l0, inv1 = 1.0f / l1;

    const int l4 = lane & 3, l2 = lane >> 2;
    long long q0 = (long long)blockIdx.x * 128 + wq * 16 + l2;
    #pragma unroll
    for (int nf = 0; nf < 16; nf++) {
        int col = nf * 8 + 2 * l4;
        long long o0 = ((long long)b * SEQ + q0) * DIM + h * HD + col;
        long long o1 = o0 + 8LL * DIM;
        *(uint32_t*)(Oh + o0) = pack_h2(oacc[nf][0] * inv0, oacc[nf][1] * inv0);
        *(uint32_t*)(Oh + o1) = pack_h2(oacc[nf][2] * inv1, oacc[nf][3] * inv1);
    }
}

// ---------------------------------------------------------------------------
extern "C" void kernel_launch(void* const* d_in, const int* in_sizes, int n_in,
                              void* d_out, int out_size)
{
    const float* x       = (const float*)d_in[0];
    const float* pe      = (const float*)d_in[1];
    const float* qkv_w   = (const float*)d_in[2];
    const float* qkv_b   = (const float*)d_in[3];
    const float* q_scale = (const float*)d_in[4];
    const float* k_scale = (const float*)d_in[5];
    const float* proj_w  = (const float*)d_in[6];
    const float* proj_b  = (const float*)d_in[7];
    float* out = (float*)d_out;

    __half *xh, *wqkvh, *wprojh, *Qnh, *Knh, *Vh, *Oh;
    cudaGetSymbolAddress((void**)&xh,     g_xh);
    cudaGetSymbolAddress((void**)&wqkvh,  g_wqkvh);
    cudaGetSymbolAddress((void**)&wprojh, g_wprojh);
    cudaGetSymbolAddress((void**)&Qnh,    g_qnh);
    cudaGetSymbolAddress((void**)&Knh,    g_knh);
    cudaGetSymbolAddress((void**)&Vh,     g_vh);
    cudaGetSymbolAddress((void**)&Oh,     g_oh);

    cudaFuncSetAttribute(gemm_f16<0>, cudaFuncAttributeMaxDynamicSharedMemorySize, GEMM_SMEM);
    cudaFuncSetAttribute(gemm_f16<1>, cudaFuncAttributeMaxDynamicSharedMemorySize, GEMM_SMEM);
    cudaFuncSetAttribute(flash_attn, cudaFuncAttributeMaxDynamicSharedMemorySize, FLASH_SMEM);

    // 0) convert inputs to fp16
    {
        long long n8;
        n8 = (long long)ROWS * DIM / 8;
        f32_to_f16<<<(unsigned)((n8 + 255) / 256), 256>>>(x, xh, n8);
        n8 = (long long)DIM * QKV_N / 8;
        f32_to_f16<<<(unsigned)((n8 + 255) / 256), 256>>>(qkv_w, wqkvh, n8);
        n8 = (long long)DIM * DIM / 8;
        f32_to_f16<<<(unsigned)((n8 + 255) / 256), 256>>>(proj_w, wprojh, n8);
    }

    // 1) fused QKV gemm -> Qnh/Knh/Vh directly
    gemm_f16<1><<<dim3(QKV_N / GBN, ROWS / GBM), 256, GEMM_SMEM>>>(
        xh, wqkvh, qkv_b, nullptr, DIM, DIM, QKV_N, 0,
        pe, q_scale, k_scale, Qnh, Knh, Vh);

    // 2) fused flash attention -> Oh fp16 in [b, l, h*D+d]
    flash_attn<<<dim3(SEQ / 128, BATCH * NH), 256, FLASH_SMEM>>>(Qnh, Knh, Vh, Oh);

    // 3) out = O @ proj_w + proj_b
    gemm_f16<0><<<dim3(DIM / GBN, ROWS / GBM), 256, GEMM_SMEM>>>(
        Oh, wprojh, proj_b, out, DIM, DIM, DIM, DIM,
        nullptr, nullptr, nullptr, nullptr, nullptr, nullptr);
}